// round 15
// baseline (speedup 1.0000x reference)
#include <cuda_runtime.h>
#include <cstdint>

#define SEQ      2048
#define BATCH    256
#define INDIM    128
#define H        256
#define NCLS     10
#define SCAN_THREADS 512

typedef unsigned long long ull;

// Scan SMEM:
//   buf : 2 phases. Entry(kp 0..127) = 2 ulonglong2 at byte
//         kp*32 + rp*16 + (kp>>5)*16  (16B pad per 32 kp -> per-ks bank skew)
//         rp0 = {row0,row1}, rp1 = {row2,row3}; each ull = {j_even, j_odd}.
//   mbar: 2 * 8B @ 8704
#define PHASE_B   4352
#define SMEM_BYTES 8720

// GEMM v4 SMEM: Bs[128 k][132] + As[64 m][132] floats -> 2 CTAs/SM
#define GEMM_SMEM ((128 * 132 + 64 * 132) * 4)
#define GEMM_CTAS_PER_HALF 148
#define M_TILES 8192          // 64-row tiles over SEQ*BATCH rows

__device__ float g_hT[H * BATCH];                    // final h, transposed [j][b]
__device__ float g_xin[(size_t)SEQ * BATCH * H];     // precomputed x @ W_ih^T

// ---------- packed f32x2 helpers ----------
__device__ __forceinline__ void ffma2(ull &d, ull a, ull b) {
    asm("fma.rn.f32x2 %0, %1, %2, %0;" : "+l"(d) : "l"(a), "l"(b));
}
__device__ __forceinline__ ull pack2(float lo, float hi) {
    ull d;
    unsigned l = __float_as_uint(lo), h = __float_as_uint(hi);
    asm("mov.b64 %0, {%1, %2};" : "=l"(d) : "r"(l), "r"(h));
    return d;
}
__device__ __forceinline__ ull dup2(float v) {
    ull d;
    unsigned u = __float_as_uint(v);
    asm("mov.b64 %0, {%1, %1};" : "=l"(d) : "r"(u));
    return d;
}
__device__ __forceinline__ void unpack2(ull a, float &lo, float &hi) {
    unsigned l, h;
    asm("mov.b64 {%0, %1}, %2;" : "=r"(l), "=r"(h) : "l"(a));
    lo = __uint_as_float(l); hi = __uint_as_float(h);
}

// Accurate tanh via __expf (~1e-7). Never tanhf -> tanh.approx (5e-4/step
// would random-walk past 1e-3 over 2048 steps).
__device__ __forceinline__ float tanh_acc(float x) {
    float a = fabsf(x);
    float e = __expf(-2.0f * a);
    float r = (1.0f - e) / (1.0f + e);
    return copysignf(r, x);
}

__device__ __forceinline__ void mbar_wait(unsigned mb, unsigned phase) {
    unsigned done;
    asm volatile(
        "{\n\t.reg .pred p;\n\t"
        "mbarrier.try_wait.parity.acquire.cluster.shared::cta.b64 p, [%1], %2;\n\t"
        "selp.b32 %0, 1, 0, p;\n\t}"
        : "=r"(done) : "r"(mb), "r"(phase) : "memory");
    if (!done) {
        asm volatile(
            "{\n\t.reg .pred P1;\n\t"
            "WL_%=:\n\t"
            "mbarrier.try_wait.parity.acquire.cluster.shared::cta.b64 P1, [%0], %1, 0x989680;\n\t"
            "@P1 bra.uni WD_%=;\n\t"
            "bra.uni WL_%=;\n\t"
            "WD_%=:\n\t}"
            :: "r"(mb), "r"(phase) : "memory");
    }
}

// ncu parity: harness issues 2 launches before ours; "-s 5 -c 1" captures
// global #6 = our launch #4. Pattern {d,d,gemm,scan,head} -> SCAN profiled.
__global__ void dummy_kernel() {}

// ============================================================================
// xin GEMM v4 (UNCHANGED R13 best: 0.80 ms, fma 61%).
// ============================================================================
__global__ void __launch_bounds__(256, 2)
xin_gemm_kernel(const float* __restrict__ x, const float* __restrict__ W_ih)
{
    extern __shared__ float sm[];
    float* Bs = sm;              // [128 k][132]
    float* As = sm + 128 * 132;  // [64 m][132]

    const int tid = threadIdx.x;
    const int nt  = blockIdx.x & 1;
    const int cta = blockIdx.x >> 1;

    for (int i = tid; i < 128 * 32; i += 256) {
        int j = i >> 5, kq = i & 31;
        float4 v = *(const float4*)(W_ih + (size_t)(nt * 128 + j) * INDIM + 4 * kq);
        Bs[(4 * kq + 0) * 132 + j] = v.x;
        Bs[(4 * kq + 1) * 132 + j] = v.y;
        Bs[(4 * kq + 2) * 132 + j] = v.z;
        Bs[(4 * kq + 3) * 132 + j] = v.w;
    }
    __syncthreads();

    const int lane = tid & 31;
    const int wrp  = tid >> 5;

    for (int mt = cta; mt < M_TILES; mt += GEMM_CTAS_PER_HALF) {
        const float4* x4 = (const float4*)(x + (size_t)mt * 64 * INDIM);
        for (int i = tid; i < 64 * 32; i += 256) {
            int m = i >> 5, kq = i & 31;
            *(float4*)(As + m * 132 + 4 * kq) = x4[m * 32 + kq];
        }
        __syncthreads();

        ull acc2[8][2];
        #pragma unroll
        for (int i = 0; i < 8; i++) { acc2[i][0] = 0; acc2[i][1] = 0; }

        for (int k = 0; k < 128; k += 4) {
            float4 a4[8];
            #pragma unroll
            for (int i = 0; i < 8; i++)
                a4[i] = *(const float4*)&As[(wrp * 8 + i) * 132 + k];
            #pragma unroll
            for (int kk = 0; kk < 4; kk++) {
                ulonglong2 b2 = *(const ulonglong2*)&Bs[(k + kk) * 132 + lane * 4];
                #pragma unroll
                for (int i = 0; i < 8; i++) {
                    float av = (kk == 0) ? a4[i].x : (kk == 1) ? a4[i].y
                             : (kk == 2) ? a4[i].z : a4[i].w;
                    ull ad = dup2(av);
                    ffma2(acc2[i][0], ad, b2.x);
                    ffma2(acc2[i][1], ad, b2.y);
                }
            }
        }

        #pragma unroll
        for (int i = 0; i < 8; i++) {
            size_t rowg = (size_t)mt * 64 + wrp * 8 + i;
            float* dst = g_xin + rowg * H + nt * 128 + lane * 4;
            float o0, o1, o2, o3;
            unpack2(acc2[i][0], o0, o1);
            unpack2(acc2[i][1], o2, o3);
            *(float4*)dst = make_float4(o0, o1, o2, o3);
        }
        __syncthreads();
    }
}

// ============================================================================
// Scan v5: 64 clusters x 2 CTAs, 4 rows/cluster, 128 j/CTA — SAME totals as
// R11 but 512 threads (16 warps, 4/SMSP) for latency hiding.
// Thread = (j 0..127 single column, ks 0..3), lane = (j&7)*4 + ks.
//   W slice 1j x 64k = 32 ull regs (~half R11's pressure).
//   Matvec: 128 ffma2 + 64 LDS.128 (4-addr broadcast, 1 wf) per thread.
//   Reduction: 2-round SCALAR shfl butterfly -> lane ks holds row ks of j.
//   Tail: 1 tanh, 4B local STS + 4B DSMEM store (st.shared::cluster.b32 with
//   integer reg — the .u32+"f" form was the R14 ptxas failure), single mbar
//   count 32 (16 local + 16 peer warp-arrives), one wait/step.
//   No syncthreads in loop.
// ============================================================================
__global__ void __cluster_dims__(2, 1, 1) __launch_bounds__(SCAN_THREADS, 1)
rnn_scan_kernel(const float* __restrict__ W_hh,
                const float* __restrict__ b_ih,
                const float* __restrict__ b_hh)
{
    extern __shared__ ull smem[];
    char* bufc = (char*)smem;            // 2 * PHASE_B
    ull*  mbar = smem + 8704 / 8;        // [2]

    const int tid = threadIdx.x;
    unsigned rank;
    asm("mov.u32 %0, %%cluster_ctarank;" : "=r"(rank));
    const int row_base = (int)(blockIdx.x >> 1) * 4;
    const int jbase    = (int)rank * 128;
    const int wid  = tid >> 5;
    const int lane = tid & 31;
    const int jl   = wid * 8 + (lane >> 2);   // 0..127 local column
    const int ks   = lane & 3;                // k-slice AND output row
    const int j    = jbase + jl;              // global column

    // ---- W_hh column slice into registers: w[i] = {W[j][ks*64+2i], +1} ----
    ull w[32];
    {
        const float4* r0 = (const float4*)(W_hh + (size_t)j * H + ks * 64);
        #pragma unroll
        for (int q = 0; q < 16; q++) {
            float4 f0 = r0[q];
            w[2 * q]     = pack2(f0.x, f0.y);
            w[2 * q + 1] = pack2(f0.z, f0.w);
        }
    }
    const float bj = b_ih[j] + b_hh[j];
    const float* xin_ptr = g_xin + (size_t)(row_base + ks) * H + j;

    const unsigned buf_lo  = (unsigned)__cvta_generic_to_shared(bufc);
    const unsigned mbar_lo = (unsigned)__cvta_generic_to_shared(mbar);
    unsigned peer_mbar;
    asm("mapa.shared::cluster.u32 %0, %1, %2;"
        : "=r"(peer_mbar) : "r"(mbar_lo), "r"(rank ^ 1u));

    // read base for k-slice ks: entry kp = ks*32+i at ks*1040 + i*32 (+rp*16)
    const char* rd0 = bufc + ks * 1040;

    // write slot: this thread produces h[j] for row ks; j lives in k-pair j>>1
    const int kpw = j >> 1;
    const unsigned off_w = (unsigned)(kpw * 32 + (ks >> 1) * 16 + (kpw >> 5) * 16
                                      + (ks & 1) * 8 + (j & 1) * 4);
    unsigned st_peer;
    {
        unsigned la = buf_lo + off_w;
        asm("mapa.shared::cluster.u32 %0, %1, %2;"
            : "=r"(st_peer) : "r"(la), "r"(rank ^ 1u));
    }

    for (int i = tid; i < 2 * PHASE_B / 8; i += SCAN_THREADS) smem[i] = 0;
    if (tid == 0) {
        asm volatile("mbarrier.init.shared.b64 [%0], 32;" :: "r"(mbar_lo) : "memory");
        asm volatile("mbarrier.init.shared.b64 [%0], 32;" :: "r"(mbar_lo + 8) : "memory");
    }
    __syncthreads();
    asm volatile("barrier.cluster.arrive.aligned;" ::: "memory");
    asm volatile("barrier.cluster.wait.aligned;"   ::: "memory");

    unsigned ph0 = 0, ph1 = 0;

    for (int s = 0; s < SEQ; s++) {
        const int cur = s & 1;
        const int nxt = cur ^ 1;

        // xin LDG issued before the wait (address independent of h; ~1000+
        // cycles of slack to the tail)
        const float xv = xin_ptr[(size_t)s * BATCH * H];

        if (s > 0) {
            unsigned phase = cur ? ph1 : ph0;
            mbar_wait(mbar_lo + (unsigned)cur * 8, phase);
            if (cur) ph1 ^= 1; else ph0 ^= 1;
        }

        // ---- matvec: 1 j x 4 rows over 64-k slice (W in regs) ----
        ull a0 = 0, a1 = 0, a2 = 0, a3 = 0;   // rows 0..3, {even,odd} packed
        const ulonglong2* hp = (const ulonglong2*)(rd0 + cur * PHASE_B);
        #pragma unroll
        for (int i = 0; i < 32; i++) {
            ulonglong2 hA = hp[2 * i];        // {row0, row1} of k-pair
            ulonglong2 hB = hp[2 * i + 1];    // {row2, row3}
            ffma2(a0, w[i], hA.x); ffma2(a1, w[i], hA.y);
            ffma2(a2, w[i], hB.x); ffma2(a3, w[i], hB.y);
        }

        // fold even/odd k -> scalars per row
        float v0, v1, v2, v3;
        {
            float e, o;
            unpack2(a0, e, o); v0 = e + o;
            unpack2(a1, e, o); v1 = e + o;
            unpack2(a2, e, o); v2 = e + o;
            unpack2(a3, e, o); v3 = e + o;
        }

        // ---- 4-way k reduction: 2-round scalar shfl butterfly over ks ----
        float r0f, r1f;
        {
            bool hi = (ks & 2) != 0;
            float keep0 = hi ? v2 : v0, keep1 = hi ? v3 : v1;
            float send0 = hi ? v0 : v2, send1 = hi ? v1 : v3;
            r0f = keep0 + __shfl_xor_sync(0xFFFFFFFFu, send0, 2);
            r1f = keep1 + __shfl_xor_sync(0xFFFFFFFFu, send1, 2);
        }
        float f;
        {
            bool hi = (ks & 1) != 0;
            float keep = hi ? r1f : r0f;
            float send = hi ? r0f : r1f;
            f = keep + __shfl_xor_sync(0xFFFFFFFFu, send, 1);
        }

        // ---- tail: bias + xin, tanh, 4B store local + peer, arrive ----
        {
            float t = tanh_acc(f + bj + xv);

            if (s == SEQ - 1) {
                g_hT[(size_t)j * BATCH + row_base + ks] = t;
            } else {
                unsigned tu = __float_as_uint(t);
                *(float*)(bufc + nxt * PHASE_B + off_w) = t;    // local
                asm volatile("st.shared::cluster.b32 [%0], %1;"
                             :: "r"(st_peer + (unsigned)nxt * PHASE_B),
                                "r"(tu) : "memory");
                __syncwarp();
                if (lane == 0) {
                    asm volatile("mbarrier.arrive.shared.b64 _, [%0];"
                                 :: "r"(mbar_lo + (unsigned)nxt * 8) : "memory");
                    asm volatile(
                        "mbarrier.arrive.release.cluster.shared::cluster.b64 _, [%0];"
                        :: "r"(peer_mbar + (unsigned)nxt * 8) : "memory");
                }
            }
        }
    }
}

// ============================================================================
// Head: logits = h_last @ W_fc^T + b_fc, softmax over the BATCH axis.
// ============================================================================
__global__ void __launch_bounds__(256)
head_kernel(const float* __restrict__ W_fc, const float* __restrict__ b_fc,
            float* __restrict__ out)
{
    __shared__ float Wsm[NCLS * H];
    __shared__ float logit[NCLS][BATCH];
    __shared__ float mred[NCLS], sred[NCLS];
    const int tid = threadIdx.x;   // = batch index b

    for (int i = tid; i < NCLS * H; i += 256) Wsm[i] = W_fc[i];
    __syncthreads();

    float acc[NCLS];
    #pragma unroll
    for (int c = 0; c < NCLS; c++) acc[c] = b_fc[c];
    #pragma unroll 1
    for (int k = 0; k < H; k += 8) {
        float hv[8];
        #pragma unroll
        for (int u = 0; u < 8; u++)
            hv[u] = g_hT[(size_t)(k + u) * BATCH + tid];
        #pragma unroll
        for (int u = 0; u < 8; u++) {
            #pragma unroll
            for (int c = 0; c < NCLS; c++)
                acc[c] += hv[u] * Wsm[c * H + k + u];
        }
    }
    #pragma unroll
    for (int c = 0; c < NCLS; c++) logit[c][tid] = acc[c];
    __syncthreads();

    if (tid < NCLS) {
        float m = -1e30f;
        for (int b = 0; b < BATCH; b++) m = fmaxf(m, logit[tid][b]);
        float ss = 0.f;
        for (int b = 0; b < BATCH; b++) ss += __expf(logit[tid][b] - m);
        mred[tid] = m;
        sred[tid] = 1.0f / ss;
    }
    __syncthreads();

    #pragma unroll
    for (int c = 0; c < NCLS; c++)
        out[tid * NCLS + c] = __expf(logit[c][tid] - mred[c]) * sred[c];
}

// ============================================================================
extern "C" void kernel_launch(void* const* d_in, const int* in_sizes, int n_in,
                              void* d_out, int out_size) {
    (void)in_sizes; (void)n_in; (void)out_size;
    const float* x    = (const float*)d_in[0];
    const float* W_ih = (const float*)d_in[1];
    const float* W_hh = (const float*)d_in[2];
    const float* b_ih = (const float*)d_in[3];
    const float* b_hh = (const float*)d_in[4];
    const float* W_fc = (const float*)d_in[5];
    const float* b_fc = (const float*)d_in[6];
    float* out = (float*)d_out;

    cudaFuncSetAttribute(xin_gemm_kernel,
                         cudaFuncAttributeMaxDynamicSharedMemorySize, GEMM_SMEM);

    // ncu parity: {d,d,gemm,scan,head} -> global #6 (-s 5 -c 1) = SCAN.
    dummy_kernel<<<1, 32>>>();
    dummy_kernel<<<1, 32>>>();
    xin_gemm_kernel<<<2 * GEMM_CTAS_PER_HALF, 256, GEMM_SMEM>>>(x, W_ih);
    rnn_scan_kernel<<<128, SCAN_THREADS, SMEM_BYTES>>>(W_hh, b_ih, b_hh);
    head_kernel<<<1, 256>>>(W_fc, b_fc, out);
}

// round 16
// speedup vs baseline: 1.4460x; 1.4460x over previous
#include <cuda_runtime.h>
#include <cstdint>

#define SEQ      2048
#define BATCH    256
#define INDIM    128
#define H        256
#define NCLS     10
#define NTHREADS 256

typedef unsigned long long ull;

// Scan SMEM (v6 layout):
//   buf : 2 phases of 4096 B. ulonglong2 entry(i 0..31, ks 0..3, rp 0..1) at
//         byte i*128 + ks*32 + rp*16, where k-pair kp = ks*32 + i.
//         Each ull = {h[2kp], h[2kp+1]} for one row; rp0={rows 0,1}, rp1={2,3}.
//         A warp's LDS.128 (4 ks-groups) hits ONE 128B line -> 1 wavefront
//         (the old per-ks 1040B skew split every load into 4 lines/4 wf).
//   mbar: 2 * 8B @ 8192
#define PHASE_B   4096
#define SMEM_BYTES 8208

// GEMM v4 SMEM: Bs[128 k][132] + As[64 m][132] floats -> 2 CTAs/SM
#define GEMM_SMEM ((128 * 132 + 64 * 132) * 4)
#define GEMM_CTAS_PER_HALF 148
#define M_TILES 8192          // 64-row tiles over SEQ*BATCH rows

__device__ float g_hT[H * BATCH];                    // final h, transposed [j][b]
__device__ float g_xin[(size_t)SEQ * BATCH * H];     // precomputed x @ W_ih^T

// ---------- packed f32x2 helpers ----------
__device__ __forceinline__ void ffma2(ull &d, ull a, ull b) {
    asm("fma.rn.f32x2 %0, %1, %2, %0;" : "+l"(d) : "l"(a), "l"(b));
}
__device__ __forceinline__ ull fadd2(ull a, ull b) {
    ull d; asm("add.rn.f32x2 %0, %1, %2;" : "=l"(d) : "l"(a), "l"(b)); return d;
}
__device__ __forceinline__ ull pack2(float lo, float hi) {
    ull d;
    unsigned l = __float_as_uint(lo), h = __float_as_uint(hi);
    asm("mov.b64 %0, {%1, %2};" : "=l"(d) : "r"(l), "r"(h));
    return d;
}
__device__ __forceinline__ ull dup2(float v) {
    ull d;
    unsigned u = __float_as_uint(v);
    asm("mov.b64 %0, {%1, %1};" : "=l"(d) : "r"(u));
    return d;
}
__device__ __forceinline__ void unpack2(ull a, float &lo, float &hi) {
    unsigned l, h;
    asm("mov.b64 {%0, %1}, %2;" : "=r"(l), "=r"(h) : "l"(a));
    lo = __uint_as_float(l); hi = __uint_as_float(h);
}

// Accurate tanh via __expf (~1e-7). Never tanhf -> tanh.approx (5e-4/step
// would random-walk past 1e-3 over 2048 steps).
__device__ __forceinline__ float tanh_acc(float x) {
    float a = fabsf(x);
    float e = __expf(-2.0f * a);
    float r = (1.0f - e) / (1.0f + e);
    return copysignf(r, x);
}

__device__ __forceinline__ void mbar_wait(unsigned mb, unsigned phase) {
    unsigned done;
    asm volatile(
        "{\n\t.reg .pred p;\n\t"
        "mbarrier.try_wait.parity.acquire.cluster.shared::cta.b64 p, [%1], %2;\n\t"
        "selp.b32 %0, 1, 0, p;\n\t}"
        : "=r"(done) : "r"(mb), "r"(phase) : "memory");
    if (!done) {
        asm volatile(
            "{\n\t.reg .pred P1;\n\t"
            "WL_%=:\n\t"
            "mbarrier.try_wait.parity.acquire.cluster.shared::cta.b64 P1, [%0], %1, 0x989680;\n\t"
            "@P1 bra.uni WD_%=;\n\t"
            "bra.uni WL_%=;\n\t"
            "WD_%=:\n\t}"
            :: "r"(mb), "r"(phase) : "memory");
    }
}

// ncu parity: harness issues 2 launches before ours; "-s 5 -c 1" captures
// global #6 = our launch #4. Pattern {d,d,gemm,scan,head} -> SCAN profiled.
__global__ void dummy_kernel() {}

// ============================================================================
// xin GEMM v4 (UNCHANGED R13 best: 0.80 ms, fma 61%).
// ============================================================================
__global__ void __launch_bounds__(256, 2)
xin_gemm_kernel(const float* __restrict__ x, const float* __restrict__ W_ih)
{
    extern __shared__ float sm[];
    float* Bs = sm;              // [128 k][132]
    float* As = sm + 128 * 132;  // [64 m][132]

    const int tid = threadIdx.x;
    const int nt  = blockIdx.x & 1;
    const int cta = blockIdx.x >> 1;

    for (int i = tid; i < 128 * 32; i += 256) {
        int j = i >> 5, kq = i & 31;
        float4 v = *(const float4*)(W_ih + (size_t)(nt * 128 + j) * INDIM + 4 * kq);
        Bs[(4 * kq + 0) * 132 + j] = v.x;
        Bs[(4 * kq + 1) * 132 + j] = v.y;
        Bs[(4 * kq + 2) * 132 + j] = v.z;
        Bs[(4 * kq + 3) * 132 + j] = v.w;
    }
    __syncthreads();

    const int lane = tid & 31;
    const int wrp  = tid >> 5;

    for (int mt = cta; mt < M_TILES; mt += GEMM_CTAS_PER_HALF) {
        const float4* x4 = (const float4*)(x + (size_t)mt * 64 * INDIM);
        for (int i = tid; i < 64 * 32; i += 256) {
            int m = i >> 5, kq = i & 31;
            *(float4*)(As + m * 132 + 4 * kq) = x4[m * 32 + kq];
        }
        __syncthreads();

        ull acc2[8][2];
        #pragma unroll
        for (int i = 0; i < 8; i++) { acc2[i][0] = 0; acc2[i][1] = 0; }

        for (int k = 0; k < 128; k += 4) {
            float4 a4[8];
            #pragma unroll
            for (int i = 0; i < 8; i++)
                a4[i] = *(const float4*)&As[(wrp * 8 + i) * 132 + k];
            #pragma unroll
            for (int kk = 0; kk < 4; kk++) {
                ulonglong2 b2 = *(const ulonglong2*)&Bs[(k + kk) * 132 + lane * 4];
                #pragma unroll
                for (int i = 0; i < 8; i++) {
                    float av = (kk == 0) ? a4[i].x : (kk == 1) ? a4[i].y
                             : (kk == 2) ? a4[i].z : a4[i].w;
                    ull ad = dup2(av);
                    ffma2(acc2[i][0], ad, b2.x);
                    ffma2(acc2[i][1], ad, b2.y);
                }
            }
        }

        #pragma unroll
        for (int i = 0; i < 8; i++) {
            size_t rowg = (size_t)mt * 64 + wrp * 8 + i;
            float* dst = g_xin + rowg * H + nt * 128 + lane * 4;
            float o0, o1, o2, o3;
            unpack2(acc2[i][0], o0, o1);
            unpack2(acc2[i][1], o2, o3);
            *(float4*)dst = make_float4(o0, o1, o2, o3);
        }
        __syncthreads();
    }
}

// ============================================================================
// Scan v6 = R11 (4435 us best) with ONLY the h layout remapped:
// 64 clusters x 2 CTAs, 4 rows/cluster, 128 j/CTA, 256 threads.
// Thread = (jp 0..63, ks 0..3), lane = jpsub*4 + ks.
//   W_hh slice (2 j x 64 k) in registers; 64 LDS.128 + 256 ffma2 per thread;
//   2-round intra-warp ull shfl butterfly; single mbar/phase count 16;
//   no __syncthreads in loop. Interleaved-ks layout -> 1 wf per h load
//   (was 4): h-read wavefronts/step 2048 -> 512.
// ============================================================================
__global__ void __cluster_dims__(2, 1, 1) __launch_bounds__(NTHREADS, 1)
rnn_scan_kernel(const float* __restrict__ W_hh,
                const float* __restrict__ b_ih,
                const float* __restrict__ b_hh)
{
    extern __shared__ ull smem[];
    char* bufc = (char*)smem;            // 2 * PHASE_B
    ull*  mbar = smem + 8192 / 8;        // [2]

    const int tid = threadIdx.x;
    unsigned rank;
    asm("mov.u32 %0, %%cluster_ctarank;" : "=r"(rank));
    const int row_base = (int)(blockIdx.x >> 1) * 4;
    const int jbase    = (int)rank * 128;
    const int wid  = tid >> 5;
    const int lane = tid & 31;
    const int jpsub = lane >> 2;              // 0..7
    const int ks    = lane & 3;               // 0..3 (k-slice AND output row)
    const int jp    = wid * 8 + jpsub;        // 0..63
    const int j0    = jbase + 2 * jp;

    // ---- W_hh slice into registers: w[j][i] = {W[j][ks*64+2i], +1} ----
    ull w0[32], w1[32];
    {
        const float4* r0 = (const float4*)(W_hh + (size_t)j0 * H + ks * 64);
        const float4* r1 = (const float4*)(W_hh + (size_t)(j0 + 1) * H + ks * 64);
        #pragma unroll
        for (int q = 0; q < 16; q++) {
            float4 f0 = r0[q], f1 = r1[q];
            w0[2 * q]     = pack2(f0.x, f0.y);
            w0[2 * q + 1] = pack2(f0.z, f0.w);
            w1[2 * q]     = pack2(f1.x, f1.y);
            w1[2 * q + 1] = pack2(f1.z, f1.w);
        }
    }
    const float bj0 = b_ih[j0] + b_hh[j0];
    const float bj1 = b_ih[j0 + 1] + b_hh[j0 + 1];
    const float* xin_ptr = g_xin + (size_t)(row_base + ks) * H + j0;

    const unsigned buf_lo  = (unsigned)__cvta_generic_to_shared(bufc);
    const unsigned mbar_lo = (unsigned)__cvta_generic_to_shared(mbar);
    unsigned peer_mbar;
    asm("mapa.shared::cluster.u32 %0, %1, %2;"
        : "=r"(peer_mbar) : "r"(mbar_lo), "r"(rank ^ 1u));

    // read base for slice ks: entry(i, ks, rp) at byte i*128 + ks*32 + rp*16
    const char* rd0 = bufc + ks * 32;

    // write slot: h-pair for k-pair kpw = rank*64 + jp, row = ks
    const int kpw = (int)rank * 64 + jp;
    const int i_w = kpw & 31, ks_w = kpw >> 5;
    const unsigned off_w = (unsigned)(i_w * 128 + ks_w * 32 + ks * 8);
    unsigned st_peer;
    {
        unsigned la = buf_lo + off_w;
        asm("mapa.shared::cluster.u32 %0, %1, %2;"
            : "=r"(st_peer) : "r"(la), "r"(rank ^ 1u));
    }

    for (int i = tid; i < 2 * PHASE_B / 8; i += NTHREADS) smem[i] = 0;
    if (tid == 0) {
        asm volatile("mbarrier.init.shared.b64 [%0], 16;" :: "r"(mbar_lo) : "memory");
        asm volatile("mbarrier.init.shared.b64 [%0], 16;" :: "r"(mbar_lo + 8) : "memory");
    }
    __syncthreads();
    asm volatile("barrier.cluster.arrive.aligned;" ::: "memory");
    asm volatile("barrier.cluster.wait.aligned;"   ::: "memory");

    unsigned ph0 = 0, ph1 = 0;

    for (int s = 0; s < SEQ; s++) {
        const int cur = s & 1;
        const int nxt = cur ^ 1;

        // xin LDG issued before the wait (address independent of h)
        const float2 xv = *(const float2*)(xin_ptr + (size_t)s * BATCH * H);

        if (s > 0) {
            unsigned phase = cur ? ph1 : ph0;
            mbar_wait(mbar_lo + (unsigned)cur * 8, phase);
            if (cur) ph1 ^= 1; else ph0 ^= 1;
        }

        // ---- matvec: 2 j x 4 rows over 64-k slice (W in regs) ----
        ull a00 = 0, a01 = 0, a02 = 0, a03 = 0;
        ull a10 = 0, a11 = 0, a12 = 0, a13 = 0;
        const ulonglong2* hp = (const ulonglong2*)(rd0 + cur * PHASE_B);
        #pragma unroll
        for (int i = 0; i < 32; i++) {
            ulonglong2 hA = hp[8 * i];        // rows {0,1} of kp = ks*32+i
            ulonglong2 hB = hp[8 * i + 1];    // rows {2,3}
            ffma2(a00, w0[i], hA.x); ffma2(a01, w0[i], hA.y);
            ffma2(a02, w0[i], hB.x); ffma2(a03, w0[i], hB.y);
            ffma2(a10, w1[i], hA.x); ffma2(a11, w1[i], hA.y);
            ffma2(a12, w1[i], hB.x); ffma2(a13, w1[i], hB.y);
        }

        ull v0, v1, v2, v3;
        {
            float e, o, e1, o1;
            unpack2(a00, e, o); unpack2(a10, e1, o1); v0 = pack2(e + o, e1 + o1);
            unpack2(a01, e, o); unpack2(a11, e1, o1); v1 = pack2(e + o, e1 + o1);
            unpack2(a02, e, o); unpack2(a12, e1, o1); v2 = pack2(e + o, e1 + o1);
            unpack2(a03, e, o); unpack2(a13, e1, o1); v3 = pack2(e + o, e1 + o1);
        }

        // ---- 4-way k reduction: 2-round shfl butterfly over ks ----
        ull k0, k1;
        {
            bool hi = (ks & 2) != 0;
            ull keep0 = hi ? v2 : v0, keep1 = hi ? v3 : v1;
            ull send0 = hi ? v0 : v2, send1 = hi ? v1 : v3;
            k0 = fadd2(keep0, __shfl_xor_sync(0xFFFFFFFFu, send0, 2));
            k1 = fadd2(keep1, __shfl_xor_sync(0xFFFFFFFFu, send1, 2));
        }
        ull f;
        {
            bool hi = (ks & 1) != 0;
            ull keep = hi ? k1 : k0;
            ull send = hi ? k0 : k1;
            f = fadd2(keep, __shfl_xor_sync(0xFFFFFFFFu, send, 1));
        }

        // ---- tail: bias + xin, tanh, store local + peer, arrive ----
        {
            float f0, f1;
            unpack2(f, f0, f1);
            float t0 = tanh_acc(f0 + bj0 + xv.x);
            float t1 = tanh_acc(f1 + bj1 + xv.y);

            if (s == SEQ - 1) {
                g_hT[(size_t)j0 * BATCH + row_base + ks]       = t0;
                g_hT[(size_t)(j0 + 1) * BATCH + row_base + ks] = t1;
            } else {
                ull dv = pack2(t0, t1);
                *(ull*)(bufc + nxt * PHASE_B + off_w) = dv;     // local
                asm volatile("st.shared::cluster.u64 [%0], %1;"
                             :: "r"(st_peer + (unsigned)nxt * PHASE_B),
                                "l"(dv) : "memory");
                __syncwarp();
                if (lane == 0) {
                    asm volatile("mbarrier.arrive.shared.b64 _, [%0];"
                                 :: "r"(mbar_lo + (unsigned)nxt * 8) : "memory");
                    asm volatile(
                        "mbarrier.arrive.release.cluster.shared::cluster.b64 _, [%0];"
                        :: "r"(peer_mbar + (unsigned)nxt * 8) : "memory");
                }
            }
        }
    }
}

// ============================================================================
// Head: logits = h_last @ W_fc^T + b_fc, softmax over the BATCH axis.
// ============================================================================
__global__ void __launch_bounds__(256)
head_kernel(const float* __restrict__ W_fc, const float* __restrict__ b_fc,
            float* __restrict__ out)
{
    __shared__ float Wsm[NCLS * H];
    __shared__ float logit[NCLS][BATCH];
    __shared__ float mred[NCLS], sred[NCLS];
    const int tid = threadIdx.x;   // = batch index b

    for (int i = tid; i < NCLS * H; i += 256) Wsm[i] = W_fc[i];
    __syncthreads();

    float acc[NCLS];
    #pragma unroll
    for (int c = 0; c < NCLS; c++) acc[c] = b_fc[c];
    #pragma unroll 1
    for (int k = 0; k < H; k += 8) {
        float hv[8];
        #pragma unroll
        for (int u = 0; u < 8; u++)
            hv[u] = g_hT[(size_t)(k + u) * BATCH + tid];
        #pragma unroll
        for (int u = 0; u < 8; u++) {
            #pragma unroll
            for (int c = 0; c < NCLS; c++)
                acc[c] += hv[u] * Wsm[c * H + k + u];
        }
    }
    #pragma unroll
    for (int c = 0; c < NCLS; c++) logit[c][tid] = acc[c];
    __syncthreads();

    if (tid < NCLS) {
        float m = -1e30f;
        for (int b = 0; b < BATCH; b++) m = fmaxf(m, logit[tid][b]);
        float ss = 0.f;
        for (int b = 0; b < BATCH; b++) ss += __expf(logit[tid][b] - m);
        mred[tid] = m;
        sred[tid] = 1.0f / ss;
    }
    __syncthreads();

    #pragma unroll
    for (int c = 0; c < NCLS; c++)
        out[tid * NCLS + c] = __expf(logit[c][tid] - mred[c]) * sred[c];
}

// ============================================================================
extern "C" void kernel_launch(void* const* d_in, const int* in_sizes, int n_in,
                              void* d_out, int out_size) {
    (void)in_sizes; (void)n_in; (void)out_size;
    const float* x    = (const float*)d_in[0];
    const float* W_ih = (const float*)d_in[1];
    const float* W_hh = (const float*)d_in[2];
    const float* b_ih = (const float*)d_in[3];
    const float* b_hh = (const float*)d_in[4];
    const float* W_fc = (const float*)d_in[5];
    const float* b_fc = (const float*)d_in[6];
    float* out = (float*)d_out;

    cudaFuncSetAttribute(xin_gemm_kernel,
                         cudaFuncAttributeMaxDynamicSharedMemorySize, GEMM_SMEM);

    // ncu parity: {d,d,gemm,scan,head} -> global #6 (-s 5 -c 1) = SCAN.
    dummy_kernel<<<1, 32>>>();
    dummy_kernel<<<1, 32>>>();
    xin_gemm_kernel<<<2 * GEMM_CTAS_PER_HALF, 256, GEMM_SMEM>>>(x, W_ih);
    rnn_scan_kernel<<<128, NTHREADS, SMEM_BYTES>>>(W_hh, b_ih, b_hh);
    head_kernel<<<1, 256>>>(W_fc, b_fc, out);
}